// round 13
// baseline (speedup 1.0000x reference)
#include <cuda_runtime.h>

#define T_ 1024
#define B_ 512
#define I_ 128
#define H_ 256

// Grid-sync recurrence kernel partitioning
#define NBR 8    // batch groups (independent barrier groups)
#define NHC 16   // h-column groups (Hc = H/NHC = 16 h-cols per CTA)
#define HC  16
#define NCTA (NBR*NHC)   // 128

#define AROW_STRIDE 392  // padded a_sh row stride in floats (384 used)
#define SMEM_BYTES (384*16*16 /*w4*/ + 32*AROW_STRIDE*4 /*a_sh*/ + 16*16 /*bias4*/)

// ---------------- device globals (scratch; no allocation allowed) ----------------
__device__ float    g_hbuf[2][B_*H_];
__device__ float    g_cbuf[B_*H_];
__device__ int      g_tstart[B_];
__device__ int      g_perm[B_];
__device__ int      g_cnt[T_];
__device__ int      g_tbegin;
__device__ unsigned g_barg[NBR];

// ---------------- init + zero: reset cross-launch state every replay ----------------
__global__ void k_zero() {
    int idx = blockIdx.x * blockDim.x + threadIdx.x;
    int stride = gridDim.x * blockDim.x;
    if (idx == 0) {
        g_tbegin = T_ - 1;
#pragma unroll
        for (int r = 0; r < NBR; ++r) g_barg[r] = 0u;
    }
    for (int i = idx; i < B_ * H_; i += stride) {
        g_hbuf[0][i] = 0.0f;
        g_hbuf[1][i] = 0.0f;
        g_cbuf[i]    = 0.0f;
    }
}

// ---------------- per-row last-reset scan ----------------
// t_start(b) = 1 + max{ t in [0,1022] : inputs[t,b,I-1] <= 0 }, or 0 if none.
__global__ void k_scan(const float* __restrict__ inp) {
    int b = blockIdx.x;
    int tid = threadIdx.x;  // 128 threads
    int best = -1;
    for (int t = tid; t < T_ - 1; t += 128) {
        float v = inp[((size_t)t * B_ + b) * I_ + (I_ - 1)];
        if (v <= 0.0f) best = t;  // ascending t -> ends at max
    }
    __shared__ int red[128];
    red[tid] = best;
    __syncthreads();
    for (int off = 64; off; off >>= 1) {
        if (tid < off) red[tid] = max(red[tid], red[tid + off]);
        __syncthreads();
    }
    if (tid == 0) {
        int ts = red[0] + 1;
        g_tstart[b] = ts;
        atomicMin(&g_tbegin, ts);
    }
}

// ---------------- counting sort by t_start + prefix counts (warp-shuffle scan) ----------------
__global__ void k_sortcnt() {
    __shared__ int hist[T_];
    __shared__ int bin[T_];
    __shared__ int wsum[32];
    int tid = threadIdx.x;  // 1024 threads
    hist[tid] = 0;
    __syncthreads();
    if (tid < B_) atomicAdd(&hist[g_tstart[tid]], 1);
    __syncthreads();
    int v = hist[tid];
    int lane = tid & 31, w = tid >> 5;
    int x = v;
#pragma unroll
    for (int o = 1; o < 32; o <<= 1) {
        int y = __shfl_up_sync(0xffffffffu, x, o);
        if (lane >= o) x += y;
    }
    if (lane == 31) wsum[w] = x;
    __syncthreads();
    if (w == 0) {
        int y = wsum[lane];
#pragma unroll
        for (int o = 1; o < 32; o <<= 1) {
            int z = __shfl_up_sync(0xffffffffu, y, o);
            if (lane >= o) y += z;
        }
        wsum[lane] = y;
    }
    __syncthreads();
    int inc = x + (w ? wsum[w - 1] : 0);   // inclusive: #rows with t_start <= tid
    g_cnt[tid] = inc;
    bin[tid] = inc - v;                    // exclusive bin offsets
    __syncthreads();
    if (tid < B_) {
        int ts = g_tstart[tid];
        int pos = atomicAdd(&bin[ts], 1);
        g_perm[pos] = tid;                 // sorted ascending by t_start
    }
}

__device__ __forceinline__ float sigf(float x) { return 1.0f / (1.0f + __expf(-x)); }

// ---------------- persistent group-synced recurrence ----------------
__global__ void __launch_bounds__(256, 1) k_lstm(
    const float* __restrict__ inp, const float* __restrict__ Wih,
    const float* __restrict__ Whh, const float* __restrict__ bih,
    const float* __restrict__ bhh)
{
    extern __shared__ float sm[];
    float4* w4    = (float4*)sm;                       // [384*16] : w4[k*16+hc] = (Wi,Wf,Wg,Wo)[col=j*16+hc][k]
    float*  a_sh  = sm + 384 * 16 * 4;                 // [32][AROW_STRIDE] staged A rows ([x|h], K=384)
    float4* bias4 = (float4*)(a_sh + 32 * AROW_STRIDE);

    const int r   = blockIdx.x & (NBR - 1);
    const int j   = blockIdx.x >> 3;
    const int tid = threadIdx.x;

    // ---- load fused weight slice into SMEM (once per launch) ----
    for (int idx = tid; idx < 384 * 16; idx += 256) {
        int k = idx >> 4, hc = idx & 15;
        int ch = j * HC + hc;
        float4 w;
        if (k < I_) {
            w.x = Wih[(0 * H_ + ch) * I_ + k];
            w.y = Wih[(1 * H_ + ch) * I_ + k];
            w.z = Wih[(2 * H_ + ch) * I_ + k];
            w.w = Wih[(3 * H_ + ch) * I_ + k];
        } else {
            int kk = k - I_;
            w.x = Whh[(0 * H_ + ch) * H_ + kk];
            w.y = Whh[(1 * H_ + ch) * H_ + kk];
            w.z = Whh[(2 * H_ + ch) * H_ + kk];
            w.w = Whh[(3 * H_ + ch) * H_ + kk];
        }
        w4[idx] = w;
    }
    if (tid < 16) {
        int ch = j * HC + tid;
        float4 bb;
        bb.x = bih[0 * H_ + ch] + bhh[0 * H_ + ch];
        bb.y = bih[1 * H_ + ch] + bhh[1 * H_ + ch];
        bb.z = bih[2 * H_ + ch] + bhh[2 * H_ + ch];
        bb.w = bih[3 * H_ + ch] + bhh[3 * H_ + ch];
        bias4[tid] = bb;
    }
    __syncthreads();

    const int warp = tid >> 5, lane = tid & 31;
    const int hc = lane & 15, s2 = lane >> 4;
    const float4 myb = bias4[hc];

    const int tb = g_tbegin;
    unsigned step = 0;

    for (int t = tb; t < T_; ++t) {
        const int n = g_cnt[t];
        const float* __restrict__ hread = g_hbuf[t & 1];
        float* __restrict__ hwrite = g_hbuf[(t + 1) & 1];
        const int mcount = (n > r) ? ((n - r + NBR - 1) >> 3) : 0;

        for (int m0 = 0; m0 < mcount; m0 += 32) {
            const int chunk = min(32, mcount - m0);

            // ---- stage up to 32 active rows: [x_t(128) | h(256)] ----
            {
                int mm = tid >> 3, l8 = tid & 7;
                if (mm < chunk) {
                    int i = r + ((m0 + mm) << 3);
                    int b = g_perm[i];
                    const float4* xin = (const float4*)(inp + ((size_t)t * B_ + b) * I_);
                    const float4* hin = (const float4*)(hread + b * H_);
                    float4* arow = (float4*)(a_sh + mm * AROW_STRIDE);
#pragma unroll
                    for (int q = 0; q < 4; ++q) arow[l8 + 8 * q] = xin[l8 + 8 * q];
#pragma unroll
                    for (int q = 0; q < 8; ++q) arow[32 + l8 + 8 * q] = hin[l8 + 8 * q];
                }
            }
            __syncthreads();

            // ---- compute gates: each lane owns (hc, 2 rows), 4 gates each ----
            const int mmA = (warp << 2) + s2;
            const int mmB = mmA + 2;
            if (mmA < chunk) {   // whole warp idles when 4*warp >= chunk
                const float* aA = a_sh + mmA * AROW_STRIDE;
                const float* aB = a_sh + mmB * AROW_STRIDE;
                float aiA = 0.f, afA = 0.f, agA = 0.f, aoA = 0.f;
                float aiB = 0.f, afB = 0.f, agB = 0.f, aoB = 0.f;

#pragma unroll 2
                for (int k = 0; k < 384; k += 4) {
                    float4 xA = *(const float4*)(aA + k);
                    float4 xB = *(const float4*)(aB + k);
                    float4 w0 = w4[(k + 0) * 16 + hc];
                    aiA += xA.x * w0.x; afA += xA.x * w0.y; agA += xA.x * w0.z; aoA += xA.x * w0.w;
                    aiB += xB.x * w0.x; afB += xB.x * w0.y; agB += xB.x * w0.z; aoB += xB.x * w0.w;
                    float4 w1 = w4[(k + 1) * 16 + hc];
                    aiA += xA.y * w1.x; afA += xA.y * w1.y; agA += xA.y * w1.z; aoA += xA.y * w1.w;
                    aiB += xB.y * w1.x; afB += xB.y * w1.y; agB += xB.y * w1.z; aoB += xB.y * w1.w;
                    float4 w2 = w4[(k + 2) * 16 + hc];
                    aiA += xA.z * w2.x; afA += xA.z * w2.y; agA += xA.z * w2.z; aoA += xA.z * w2.w;
                    aiB += xB.z * w2.x; afB += xB.z * w2.y; agB += xB.z * w2.z; aoB += xB.z * w2.w;
                    float4 w3 = w4[(k + 3) * 16 + hc];
                    aiA += xA.w * w3.x; afA += xA.w * w3.y; agA += xA.w * w3.z; aoA += xA.w * w3.w;
                    aiB += xB.w * w3.x; afB += xB.w * w3.y; agB += xB.w * w3.z; aoB += xB.w * w3.w;
                }

                // ---- epilogue: activations + cell/hidden update ----
                const int col = j * HC + hc;
                {
                    int i = r + ((m0 + mmA) << 3);
                    int b = g_perm[i];
                    float gi = sigf(aiA + myb.x);
                    float gf = sigf(afA + myb.y);
                    float gg = tanhf(agA + myb.z);
                    float go = sigf(aoA + myb.w);
                    float c = g_cbuf[b * H_ + col];
                    float cn = gf * c + gi * gg;
                    g_cbuf[b * H_ + col] = cn;
                    hwrite[b * H_ + col] = go * tanhf(cn);
                }
                if (mmB < chunk) {
                    int i = r + ((m0 + mmB) << 3);
                    int b = g_perm[i];
                    float gi = sigf(aiB + myb.x);
                    float gf = sigf(afB + myb.y);
                    float gg = tanhf(agB + myb.z);
                    float go = sigf(aoB + myb.w);
                    float c = g_cbuf[b * H_ + col];
                    float cn = gf * c + gi * gg;
                    g_cbuf[b * H_ + col] = cn;
                    hwrite[b * H_ + col] = go * tanhf(cn);
                }
            }
            __syncthreads();
        }

        if (t == T_ - 1) break;   // no barrier needed after the last step

        // ---- per-r-group software barrier (release/acquire; 16 resident CTAs) ----
        step++;
        __syncthreads();
        if (tid == 0) {
            __threadfence();
            atomicAdd(&g_barg[r], 1u);
            unsigned target = step * (unsigned)NHC;
            unsigned v;
            do {
                asm volatile("ld.acquire.gpu.u32 %0, [%1];" : "=r"(v) : "l"(&g_barg[r]) : "memory");
            } while (v < target);
        }
        __syncthreads();
    }
}

// ---------------- output GEMV: out[b] = h_last[b,:] . W_out + b_out ----------------
__global__ void k_out(const float* __restrict__ Wout, const float* __restrict__ bout,
                      float* __restrict__ out) {
    int warp = threadIdx.x >> 5, lane = threadIdx.x & 31;
    int b = blockIdx.x * 8 + warp;
    // final step writes hbuf[(1023+1)&1] = hbuf[0] for all rows
    const float* h = g_hbuf[0] + b * H_;
    float ssum = 0.0f;
#pragma unroll
    for (int k = lane; k < H_; k += 32) ssum += h[k] * Wout[k];
#pragma unroll
    for (int off = 16; off; off >>= 1) ssum += __shfl_xor_sync(0xffffffffu, ssum, off);
    if (lane == 0) out[b] = ssum + bout[0];
}

extern "C" void kernel_launch(void* const* d_in, const int* in_sizes, int n_in,
                              void* d_out, int out_size) {
    (void)in_sizes; (void)n_in; (void)out_size;
    const float* inp  = (const float*)d_in[0];
    const float* Wih  = (const float*)d_in[1];
    const float* Whh  = (const float*)d_in[2];
    const float* bih  = (const float*)d_in[3];
    const float* bhh  = (const float*)d_in[4];
    const float* Wout = (const float*)d_in[5];
    const float* bout = (const float*)d_in[6];
    float* out = (float*)d_out;

    cudaFuncSetAttribute(k_lstm, cudaFuncAttributeMaxDynamicSharedMemorySize, SMEM_BYTES);

    k_zero<<<256, 256>>>();
    k_scan<<<B_, 128>>>(inp);
    k_sortcnt<<<1, 1024>>>();
    k_lstm<<<NCTA, 256, SMEM_BYTES>>>(inp, Wih, Whh, bih, bhh);
    k_out<<<B_ / 8, 256>>>(Wout, bout, out);
}

// round 14
// speedup vs baseline: 1.0029x; 1.0029x over previous
#include <cuda_runtime.h>

#define T_ 1024
#define B_ 512
#define I_ 128
#define H_ 256

// Grid-sync recurrence kernel partitioning
#define NBR 8    // batch groups (independent barrier groups)
#define NHC 16   // h-column groups (Hc = H/NHC = 16 h-cols per CTA)
#define HC  16
#define NCTA (NBR*NHC)   // 128

#define AROW_STRIDE 392  // padded a_sh row stride in floats (384 used)
#define SMEM_BYTES (384*16*16 /*w4*/ + 32*AROW_STRIDE*4 /*a_sh*/ + 16*16 /*bias4*/)

// ---------------- device globals (scratch; no allocation allowed) ----------------
__device__ float    g_hbuf[2][B_*H_];
__device__ float    g_cbuf[B_*H_];
__device__ int      g_tstart[B_];
__device__ int      g_perm[B_];
__device__ int      g_cnt[T_];
__device__ int      g_tbegin;
__device__ unsigned g_barg[NBR];

// ---------------- init + zero: reset cross-launch state every replay ----------------
__global__ void k_zero() {
    int idx = blockIdx.x * blockDim.x + threadIdx.x;
    int stride = gridDim.x * blockDim.x;
    if (idx == 0) {
        g_tbegin = T_ - 1;
#pragma unroll
        for (int r = 0; r < NBR; ++r) g_barg[r] = 0u;
    }
    for (int i = idx; i < B_ * H_; i += stride) {
        g_hbuf[0][i] = 0.0f;
        g_hbuf[1][i] = 0.0f;
        g_cbuf[i]    = 0.0f;
    }
}

// ---------------- per-row last-reset scan ----------------
// t_start(b) = 1 + max{ t in [0,1022] : inputs[t,b,I-1] <= 0 }, or 0 if none.
__global__ void k_scan(const float* __restrict__ inp) {
    int b = blockIdx.x;
    int tid = threadIdx.x;  // 128 threads
    int best = -1;
    for (int t = tid; t < T_ - 1; t += 128) {
        float v = inp[((size_t)t * B_ + b) * I_ + (I_ - 1)];
        if (v <= 0.0f) best = t;  // ascending t -> ends at max
    }
    __shared__ int red[128];
    red[tid] = best;
    __syncthreads();
    for (int off = 64; off; off >>= 1) {
        if (tid < off) red[tid] = max(red[tid], red[tid + off]);
        __syncthreads();
    }
    if (tid == 0) {
        int ts = red[0] + 1;
        g_tstart[b] = ts;
        atomicMin(&g_tbegin, ts);
    }
}

// ---------------- counting sort by t_start + prefix counts (warp-shuffle scan) ----------------
__global__ void k_sortcnt() {
    __shared__ int hist[T_];
    __shared__ int bin[T_];
    __shared__ int wsum[32];
    int tid = threadIdx.x;  // 1024 threads
    hist[tid] = 0;
    __syncthreads();
    if (tid < B_) atomicAdd(&hist[g_tstart[tid]], 1);
    __syncthreads();
    int v = hist[tid];
    int lane = tid & 31, w = tid >> 5;
    int x = v;
#pragma unroll
    for (int o = 1; o < 32; o <<= 1) {
        int y = __shfl_up_sync(0xffffffffu, x, o);
        if (lane >= o) x += y;
    }
    if (lane == 31) wsum[w] = x;
    __syncthreads();
    if (w == 0) {
        int y = wsum[lane];
#pragma unroll
        for (int o = 1; o < 32; o <<= 1) {
            int z = __shfl_up_sync(0xffffffffu, y, o);
            if (lane >= o) y += z;
        }
        wsum[lane] = y;
    }
    __syncthreads();
    int inc = x + (w ? wsum[w - 1] : 0);   // inclusive: #rows with t_start <= tid
    g_cnt[tid] = inc;
    bin[tid] = inc - v;                    // exclusive bin offsets
    __syncthreads();
    if (tid < B_) {
        int ts = g_tstart[tid];
        int pos = atomicAdd(&bin[ts], 1);
        g_perm[pos] = tid;                 // sorted ascending by t_start
    }
}

__device__ __forceinline__ float sigf(float x) { return 1.0f / (1.0f + __expf(-x)); }

// ---------------- persistent group-synced recurrence ----------------
__global__ void __launch_bounds__(256, 1) k_lstm(
    const float* __restrict__ inp, const float* __restrict__ Wih,
    const float* __restrict__ Whh, const float* __restrict__ bih,
    const float* __restrict__ bhh)
{
    extern __shared__ float sm[];
    float4* w4    = (float4*)sm;                       // [384*16] : w4[k*16+hc] = (Wi,Wf,Wg,Wo)[col=j*16+hc][k]
    float*  a_sh  = sm + 384 * 16 * 4;                 // [32][AROW_STRIDE] staged A rows ([x|h], K=384)
    float4* bias4 = (float4*)(a_sh + 32 * AROW_STRIDE);

    const int r   = blockIdx.x & (NBR - 1);
    const int j   = blockIdx.x >> 3;
    const int tid = threadIdx.x;

    // ---- load fused weight slice into SMEM (once per launch) ----
    for (int idx = tid; idx < 384 * 16; idx += 256) {
        int k = idx >> 4, hc = idx & 15;
        int ch = j * HC + hc;
        float4 w;
        if (k < I_) {
            w.x = Wih[(0 * H_ + ch) * I_ + k];
            w.y = Wih[(1 * H_ + ch) * I_ + k];
            w.z = Wih[(2 * H_ + ch) * I_ + k];
            w.w = Wih[(3 * H_ + ch) * I_ + k];
        } else {
            int kk = k - I_;
            w.x = Whh[(0 * H_ + ch) * H_ + kk];
            w.y = Whh[(1 * H_ + ch) * H_ + kk];
            w.z = Whh[(2 * H_ + ch) * H_ + kk];
            w.w = Whh[(3 * H_ + ch) * H_ + kk];
        }
        w4[idx] = w;
    }
    if (tid < 16) {
        int ch = j * HC + tid;
        float4 bb;
        bb.x = bih[0 * H_ + ch] + bhh[0 * H_ + ch];
        bb.y = bih[1 * H_ + ch] + bhh[1 * H_ + ch];
        bb.z = bih[2 * H_ + ch] + bhh[2 * H_ + ch];
        bb.w = bih[3 * H_ + ch] + bhh[3 * H_ + ch];
        bias4[tid] = bb;
    }
    __syncthreads();

    const int warp = tid >> 5, lane = tid & 31;
    const int hc = lane & 15, s2 = lane >> 4;
    const float4 myb = bias4[hc];

    const int tb = g_tbegin;
    unsigned step = 0;

    for (int t = tb; t < T_; ++t) {
        const int n = g_cnt[t];
        const float* __restrict__ hread = g_hbuf[t & 1];
        float* __restrict__ hwrite = g_hbuf[(t + 1) & 1];
        const int mcount = (n > r) ? ((n - r + NBR - 1) >> 3) : 0;

        for (int m0 = 0; m0 < mcount; m0 += 32) {
            const int chunk = min(32, mcount - m0);

            // ---- stage up to 32 active rows: [x_t(128) | h(256)] ----
            {
                int mm = tid >> 3, l8 = tid & 7;
                if (mm < chunk) {
                    int i = r + ((m0 + mm) << 3);
                    int b = g_perm[i];
                    const float4* xin = (const float4*)(inp + ((size_t)t * B_ + b) * I_);
                    const float4* hin = (const float4*)(hread + b * H_);
                    float4* arow = (float4*)(a_sh + mm * AROW_STRIDE);
#pragma unroll
                    for (int q = 0; q < 4; ++q) arow[l8 + 8 * q] = xin[l8 + 8 * q];
#pragma unroll
                    for (int q = 0; q < 8; ++q) arow[32 + l8 + 8 * q] = hin[l8 + 8 * q];
                }
            }
            __syncthreads();

            // ---- compute gates: each lane owns (hc, 2 rows), 4 gates each ----
            const int mmA = (warp << 2) + s2;
            const int mmB = mmA + 2;
            if (mmA < chunk) {   // whole warp idles when 4*warp >= chunk
                const float* aA = a_sh + mmA * AROW_STRIDE;
                const float* aB = a_sh + mmB * AROW_STRIDE;
                float aiA = 0.f, afA = 0.f, agA = 0.f, aoA = 0.f;
                float aiB = 0.f, afB = 0.f, agB = 0.f, aoB = 0.f;

#pragma unroll 2
                for (int k = 0; k < 384; k += 4) {
                    float4 xA = *(const float4*)(aA + k);
                    float4 xB = *(const float4*)(aB + k);
                    float4 w0 = w4[(k + 0) * 16 + hc];
                    aiA += xA.x * w0.x; afA += xA.x * w0.y; agA += xA.x * w0.z; aoA += xA.x * w0.w;
                    aiB += xB.x * w0.x; afB += xB.x * w0.y; agB += xB.x * w0.z; aoB += xB.x * w0.w;
                    float4 w1 = w4[(k + 1) * 16 + hc];
                    aiA += xA.y * w1.x; afA += xA.y * w1.y; agA += xA.y * w1.z; aoA += xA.y * w1.w;
                    aiB += xB.y * w1.x; afB += xB.y * w1.y; agB += xB.y * w1.z; aoB += xB.y * w1.w;
                    float4 w2 = w4[(k + 2) * 16 + hc];
                    aiA += xA.z * w2.x; afA += xA.z * w2.y; agA += xA.z * w2.z; aoA += xA.z * w2.w;
                    aiB += xB.z * w2.x; afB += xB.z * w2.y; agB += xB.z * w2.z; aoB += xB.z * w2.w;
                    float4 w3 = w4[(k + 3) * 16 + hc];
                    aiA += xA.w * w3.x; afA += xA.w * w3.y; agA += xA.w * w3.z; aoA += xA.w * w3.w;
                    aiB += xB.w * w3.x; afB += xB.w * w3.y; agB += xB.w * w3.z; aoB += xB.w * w3.w;
                }

                // ---- epilogue: activations + cell/hidden update ----
                const int col = j * HC + hc;
                {
                    int i = r + ((m0 + mmA) << 3);
                    int b = g_perm[i];
                    float gi = sigf(aiA + myb.x);
                    float gf = sigf(afA + myb.y);
                    float gg = tanhf(agA + myb.z);
                    float go = sigf(aoA + myb.w);
                    float c = g_cbuf[b * H_ + col];
                    float cn = gf * c + gi * gg;
                    g_cbuf[b * H_ + col] = cn;
                    hwrite[b * H_ + col] = go * tanhf(cn);
                }
                if (mmB < chunk) {
                    int i = r + ((m0 + mmB) << 3);
                    int b = g_perm[i];
                    float gi = sigf(aiB + myb.x);
                    float gf = sigf(afB + myb.y);
                    float gg = tanhf(agB + myb.z);
                    float go = sigf(aoB + myb.w);
                    float c = g_cbuf[b * H_ + col];
                    float cn = gf * c + gi * gg;
                    g_cbuf[b * H_ + col] = cn;
                    hwrite[b * H_ + col] = go * tanhf(cn);
                }
            }
            __syncthreads();
        }

        if (t == T_ - 1) break;   // no barrier needed after the last step

        // ---- per-r-group software barrier (release/acquire; 16 resident CTAs) ----
        step++;
        __syncthreads();
        if (tid == 0) {
            __threadfence();
            atomicAdd(&g_barg[r], 1u);
            unsigned target = step * (unsigned)NHC;
            unsigned v;
            do {
                asm volatile("ld.acquire.gpu.u32 %0, [%1];" : "=r"(v) : "l"(&g_barg[r]) : "memory");
            } while (v < target);
        }
        __syncthreads();
    }
}

// ---------------- output GEMV: out[b] = h_last[b,:] . W_out + b_out ----------------
__global__ void k_out(const float* __restrict__ Wout, const float* __restrict__ bout,
                      float* __restrict__ out) {
    int warp = threadIdx.x >> 5, lane = threadIdx.x & 31;
    int b = blockIdx.x * 8 + warp;
    // final step writes hbuf[(1023+1)&1] = hbuf[0] for all rows
    const float* h = g_hbuf[0] + b * H_;
    float ssum = 0.0f;
#pragma unroll
    for (int k = lane; k < H_; k += 32) ssum += h[k] * Wout[k];
#pragma unroll
    for (int off = 16; off; off >>= 1) ssum += __shfl_xor_sync(0xffffffffu, ssum, off);
    if (lane == 0) out[b] = ssum + bout[0];
}

extern "C" void kernel_launch(void* const* d_in, const int* in_sizes, int n_in,
                              void* d_out, int out_size) {
    (void)in_sizes; (void)n_in; (void)out_size;
    const float* inp  = (const float*)d_in[0];
    const float* Wih  = (const float*)d_in[1];
    const float* Whh  = (const float*)d_in[2];
    const float* bih  = (const float*)d_in[3];
    const float* bhh  = (const float*)d_in[4];
    const float* Wout = (const float*)d_in[5];
    const float* bout = (const float*)d_in[6];
    float* out = (float*)d_out;

    cudaFuncSetAttribute(k_lstm, cudaFuncAttributeMaxDynamicSharedMemorySize, SMEM_BYTES);

    k_zero<<<256, 256>>>();
    k_scan<<<B_, 128>>>(inp);
    k_sortcnt<<<1, 1024>>>();
    k_lstm<<<NCTA, 256, SMEM_BYTES>>>(inp, Wih, Whh, bih, bhh);
    k_out<<<B_ / 8, 256>>>(Wout, bout, out);
}

// round 15
// speedup vs baseline: 1.2871x; 1.2833x over previous
#include <cuda_runtime.h>

#define T_ 1024
#define B_ 512
#define I_ 128
#define H_ 256

#define NBR 8    // batch groups (independent barrier groups)
#define NHC 16   // h-column groups (16 h-cols per CTA)
#define HC  16
#define NCTA (NBR*NHC)   // 128

#define AROW_STRIDE 392   // padded a_sh row stride in floats (384 used)
#define WPAIRS 192        // K pairs (K=384)
// smem: wIF[192*16] float4 + wGO[192*16] float4 + a_sh[32*392] f32 + bias4[16]
#define SMEM_BYTES ((WPAIRS*16*4*2 + 32*AROW_STRIDE + 16*4)*4)

// ---------------- device globals ----------------
__device__ float    g_hbuf[2][B_*H_];
__device__ float    g_cbuf[B_*H_];
__device__ int      g_tstart[B_];
__device__ int      g_perm[B_];
__device__ int      g_cnt[T_];
__device__ int      g_tbegin;
__device__ unsigned g_barg[NBR];

// ---------------- tiny init (out = b_out, counters) ----------------
__global__ void k_zero(const float* __restrict__ bout, float* __restrict__ out) {
    int tid = threadIdx.x;  // 512
    out[tid] = bout[0];
    if (tid < NBR) g_barg[tid] = 0u;
    if (tid == 0) g_tbegin = T_ - 1;
}

// ---------------- per-row last-reset scan ----------------
__global__ void k_scan(const float* __restrict__ inp) {
    int b = blockIdx.x;
    int tid = threadIdx.x;  // 128
    int best = -1;
    for (int t = tid; t < T_ - 1; t += 128) {
        float v = inp[((size_t)t * B_ + b) * I_ + (I_ - 1)];
        if (v <= 0.0f) best = t;
    }
    __shared__ int red[128];
    red[tid] = best;
    __syncthreads();
    for (int off = 64; off; off >>= 1) {
        if (tid < off) red[tid] = max(red[tid], red[tid + off]);
        __syncthreads();
    }
    if (tid == 0) {
        int ts = red[0] + 1;
        g_tstart[b] = ts;
        atomicMin(&g_tbegin, ts);
    }
}

// ---------------- counting sort + prefix counts ----------------
__global__ void k_sortcnt() {
    __shared__ int hist[T_];
    __shared__ int bin[T_];
    __shared__ int wsum[32];
    int tid = threadIdx.x;  // 1024
    hist[tid] = 0;
    __syncthreads();
    if (tid < B_) atomicAdd(&hist[g_tstart[tid]], 1);
    __syncthreads();
    int v = hist[tid];
    int lane = tid & 31, w = tid >> 5;
    int x = v;
#pragma unroll
    for (int o = 1; o < 32; o <<= 1) {
        int y = __shfl_up_sync(0xffffffffu, x, o);
        if (lane >= o) x += y;
    }
    if (lane == 31) wsum[w] = x;
    __syncthreads();
    if (w == 0) {
        int y = wsum[lane];
#pragma unroll
        for (int o = 1; o < 32; o <<= 1) {
            int z = __shfl_up_sync(0xffffffffu, y, o);
            if (lane >= o) y += z;
        }
        wsum[lane] = y;
    }
    __syncthreads();
    int inc = x + (w ? wsum[w - 1] : 0);
    g_cnt[tid] = inc;
    bin[tid] = inc - v;
    __syncthreads();
    if (tid < B_) {
        int ts = g_tstart[tid];
        int pos = atomicAdd(&bin[ts], 1);
        g_perm[pos] = tid;
    }
}

__device__ __forceinline__ float sigf(float x) { return 1.0f / (1.0f + __expf(-x)); }

__device__ __forceinline__ void fma2(unsigned long long& acc, unsigned long long a,
                                     unsigned long long b) {
    asm("fma.rn.f32x2 %0, %1, %2, %0;" : "+l"(acc) : "l"(a), "l"(b));
}
__device__ __forceinline__ float unpack_sum(unsigned long long v) {
    float lo, hi;
    asm("mov.b64 {%0,%1}, %2;" : "=f"(lo), "=f"(hi) : "l"(v));
    return lo + hi;
}

// ---- compute NR rows (row = warp + 8q), K-half split over s2, packed f32x2 ----
template <int NR>
__device__ __forceinline__ void do_rows(
    const float* __restrict__ a_sh, const float4* __restrict__ wIF4,
    const float4* __restrict__ wGO4, int warp, int hc, int s2, int m0, int rgrp,
    int col, float4 myb, float* __restrict__ hwrite, const int* __restrict__ perm,
    float* __restrict__ cbuf, int n_prev, bool last, float wout_col,
    float* __restrict__ out)
{
    unsigned long long ai[NR], af[NR], ag[NR], ao[NR];
#pragma unroll
    for (int q = 0; q < NR; ++q) { ai[q] = af[q] = ag[q] = ao[q] = 0ull; }

    const int P0 = s2 * 96;
#pragma unroll 4
    for (int p = P0; p < P0 + 96; p += 2) {
        ulonglong2 wif0 = *(const ulonglong2*)&wIF4[(p    ) * 16 + hc];
        ulonglong2 wgo0 = *(const ulonglong2*)&wGO4[(p    ) * 16 + hc];
        ulonglong2 wif1 = *(const ulonglong2*)&wIF4[(p + 1) * 16 + hc];
        ulonglong2 wgo1 = *(const ulonglong2*)&wGO4[(p + 1) * 16 + hc];
#pragma unroll
        for (int q = 0; q < NR; ++q) {
            const ulonglong2 xx =
                *(const ulonglong2*)(a_sh + (warp + 8 * q) * AROW_STRIDE + 2 * p);
            fma2(ai[q], xx.x, wif0.x); fma2(af[q], xx.x, wif0.y);
            fma2(ag[q], xx.x, wgo0.x); fma2(ao[q], xx.x, wgo0.y);
            fma2(ai[q], xx.y, wif1.x); fma2(af[q], xx.y, wif1.y);
            fma2(ag[q], xx.y, wgo1.x); fma2(ao[q], xx.y, wgo1.y);
        }
    }

    const unsigned hmask = s2 ? 0xffff0000u : 0x0000ffffu;
#pragma unroll
    for (int q = 0; q < NR; ++q) {
        float si = unpack_sum(ai[q]);
        float sf = unpack_sum(af[q]);
        float sg = unpack_sum(ag[q]);
        float so = unpack_sum(ao[q]);
        // combine K-halves (full warp converged here)
        si += __shfl_xor_sync(0xffffffffu, si, 16);
        sf += __shfl_xor_sync(0xffffffffu, sf, 16);
        sg += __shfl_xor_sync(0xffffffffu, sg, 16);
        so += __shfl_xor_sync(0xffffffffu, so, 16);
        if ((q & 1) == s2) {   // uniform per 16-lane half
            int i = rgrp + (m0 + warp + 8 * q) * 8;
            int b = perm[i];
            float gi = sigf(si + myb.x);
            float gf = sigf(sf + myb.y);
            float gg = tanhf(sg + myb.z);
            float go = sigf(so + myb.w);
            float c  = (i >= n_prev) ? 0.0f : cbuf[b * H_ + col];
            float cn = gf * c + gi * gg;
            float hn = go * tanhf(cn);
            if (!last) {
                cbuf[b * H_ + col]   = cn;
                hwrite[b * H_ + col] = hn;
            } else {
                float vv = hn * wout_col;
                vv += __shfl_xor_sync(hmask, vv, 8);
                vv += __shfl_xor_sync(hmask, vv, 4);
                vv += __shfl_xor_sync(hmask, vv, 2);
                vv += __shfl_xor_sync(hmask, vv, 1);
                if (hc == 0) atomicAdd(&out[b], vv);
            }
        }
    }
}

// ---------------- persistent group-synced recurrence ----------------
__global__ void __launch_bounds__(256, 1) k_lstm(
    const float* __restrict__ inp, const float* __restrict__ Wih,
    const float* __restrict__ Whh, const float* __restrict__ bih,
    const float* __restrict__ bhh, const float* __restrict__ Wout,
    float* __restrict__ out)
{
    extern __shared__ float sm[];
    float4* wIF4  = (float4*)sm;                          // [192*16]: (i0,i1,f0,f1)
    float4* wGO4  = wIF4 + WPAIRS * 16;                   // [192*16]: (g0,g1,o0,o1)
    float*  a_sh  = sm + WPAIRS * 16 * 4 * 2;             // [32][392]
    float4* bias4 = (float4*)(a_sh + 32 * AROW_STRIDE);   // [16]

    const int rgrp = blockIdx.x & (NBR - 1);
    const int j    = blockIdx.x >> 3;
    const int tid  = threadIdx.x;

    // ---- repack weight slice into SMEM as (pair, hc, gates) ----
    for (int idx = tid; idx < WPAIRS * 16; idx += 256) {
        int p = idx >> 4, hc0 = idx & 15;
        int ch = j * HC + hc0;
        int k0 = 2 * p;
        const float* Wsrc; int kk, ld;
        if (k0 < I_) { Wsrc = Wih; kk = k0;      ld = I_; }
        else         { Wsrc = Whh; kk = k0 - I_; ld = H_; }
        float i0 = Wsrc[(0 * H_ + ch) * ld + kk], i1 = Wsrc[(0 * H_ + ch) * ld + kk + 1];
        float f0 = Wsrc[(1 * H_ + ch) * ld + kk], f1 = Wsrc[(1 * H_ + ch) * ld + kk + 1];
        float g0 = Wsrc[(2 * H_ + ch) * ld + kk], g1 = Wsrc[(2 * H_ + ch) * ld + kk + 1];
        float o0 = Wsrc[(3 * H_ + ch) * ld + kk], o1 = Wsrc[(3 * H_ + ch) * ld + kk + 1];
        wIF4[idx] = make_float4(i0, i1, f0, f1);
        wGO4[idx] = make_float4(g0, g1, o0, o1);
    }
    if (tid < 16) {
        int ch = j * HC + tid;
        float4 bb;
        bb.x = bih[0 * H_ + ch] + bhh[0 * H_ + ch];
        bb.y = bih[1 * H_ + ch] + bhh[1 * H_ + ch];
        bb.z = bih[2 * H_ + ch] + bhh[2 * H_ + ch];
        bb.w = bih[3 * H_ + ch] + bhh[3 * H_ + ch];
        bias4[tid] = bb;
    }
    __syncthreads();

    const int warp = tid >> 5, lane = tid & 31;
    const int hc = lane & 15, s2 = lane >> 4;
    const int col = j * HC + hc;
    const float4 myb = bias4[hc];
    const float wout_col = Wout[col];

    const int tb = g_tbegin;
    unsigned step = 0;

    for (int t = tb; t < T_; ++t) {
        const int n = g_cnt[t];
        const int n_prev = (t > 0) ? g_cnt[t - 1] : 0;
        const float* __restrict__ hread = g_hbuf[t & 1];
        float* __restrict__ hwrite = g_hbuf[(t + 1) & 1];
        const int mcount = (n > rgrp) ? ((n - rgrp + NBR - 1) >> 3) : 0;
        const bool last = (t == T_ - 1);

        for (int m0 = 0; m0 < mcount; m0 += 32) {
            const int chunk = min(32, mcount - m0);

            // ---- stage up to 32 active rows: [x_t(128) | h(256)] ----
            {
                int mm = tid >> 3, l8 = tid & 7;
                if (mm < chunk) {
                    int i = rgrp + (m0 + mm) * 8;
                    int b = g_perm[i];
                    const float4* xin = (const float4*)(inp + ((size_t)t * B_ + b) * I_);
                    float4* arow = (float4*)(a_sh + mm * AROW_STRIDE);
#pragma unroll
                    for (int q = 0; q < 4; ++q) arow[l8 + 8 * q] = xin[l8 + 8 * q];
                    if (i >= n_prev) {
                        float4 z = make_float4(0.f, 0.f, 0.f, 0.f);
#pragma unroll
                        for (int q = 0; q < 8; ++q) arow[32 + l8 + 8 * q] = z;
                    } else {
                        const float4* hin = (const float4*)(hread + b * H_);
#pragma unroll
                        for (int q = 0; q < 8; ++q) arow[32 + l8 + 8 * q] = hin[l8 + 8 * q];
                    }
                }
            }
            __syncthreads();

            const int avail = chunk - warp;
            if (avail > 0) {
                const int nr = ((avail - 1) >> 3) + 1;  // rows for this warp: warp+8q
                switch (nr) {
                    case 1: do_rows<1>(a_sh, wIF4, wGO4, warp, hc, s2, m0, rgrp, col, myb,
                                       hwrite, g_perm, g_cbuf, n_prev, last, wout_col, out); break;
                    case 2: do_rows<2>(a_sh, wIF4, wGO4, warp, hc, s2, m0, rgrp, col, myb,
                                       hwrite, g_perm, g_cbuf, n_prev, last, wout_col, out); break;
                    case 3: do_rows<3>(a_sh, wIF4, wGO4, warp, hc, s2, m0, rgrp, col, myb,
                                       hwrite, g_perm, g_cbuf, n_prev, last, wout_col, out); break;
                    default: do_rows<4>(a_sh, wIF4, wGO4, warp, hc, s2, m0, rgrp, col, myb,
                                        hwrite, g_perm, g_cbuf, n_prev, last, wout_col, out); break;
                }
            }
            __syncthreads();
        }

        if (last) break;

        // ---- per-r-group software barrier (16 CTAs) ----
        step++;
        __syncthreads();
        if (tid == 0) {
            __threadfence();
            atomicAdd(&g_barg[rgrp], 1u);
            unsigned target = step * (unsigned)NHC;
            unsigned v;
            do {
                asm volatile("ld.acquire.gpu.u32 %0, [%1];" : "=r"(v) : "l"(&g_barg[rgrp]) : "memory");
            } while (v < target);
        }
        __syncthreads();
    }
}

extern "C" void kernel_launch(void* const* d_in, const int* in_sizes, int n_in,
                              void* d_out, int out_size) {
    (void)in_sizes; (void)n_in; (void)out_size;
    const float* inp  = (const float*)d_in[0];
    const float* Wih  = (const float*)d_in[1];
    const float* Whh  = (const float*)d_in[2];
    const float* bih  = (const float*)d_in[3];
    const float* bhh  = (const float*)d_in[4];
    const float* Wout = (const float*)d_in[5];
    const float* bout = (const float*)d_in[6];
    float* out = (float*)d_out;

    cudaFuncSetAttribute(k_lstm, cudaFuncAttributeMaxDynamicSharedMemorySize, SMEM_BYTES);

    k_zero<<<1, 512>>>(bout, out);
    k_scan<<<B_, 128>>>(inp);
    k_sortcnt<<<1, 1024>>>();
    k_lstm<<<NCTA, 256, SMEM_BYTES>>>(inp, Wih, Whh, bih, bhh, Wout, out);
}

// round 16
// speedup vs baseline: 1.2905x; 1.0027x over previous
#include <cuda_runtime.h>

#define T_ 1024
#define B_ 512
#define I_ 128
#define H_ 256

#define NBR 8    // batch groups (independent barrier groups)
#define NHC 16   // h-column groups (16 h-cols per CTA)
#define HC  16
#define NCTA (NBR*NHC)   // 128

#define AROW_STRIDE 392   // padded a_sh row stride in floats (384 used)
#define WPAIRS 192        // K pairs (K=384)
// smem: wIF[192*16] float4 + wGO[192*16] float4 + a_sh[32*392] f32 + bias4[16]
#define SMEM_BYTES ((WPAIRS*16*4*2 + 32*AROW_STRIDE + 16*4)*4)

// ---------------- device globals ----------------
__device__ float    g_hbuf[2][B_*H_];
__device__ float    g_cbuf[B_*H_];
__device__ int      g_tstart[B_];
__device__ int      g_perm[B_];
__device__ int      g_cnt[T_];
__device__ int      g_tbegin;
__device__ unsigned g_barg[NBR];

// ---------------- tiny init (out = b_out, counters) ----------------
__global__ void k_zero(const float* __restrict__ bout, float* __restrict__ out) {
    int tid = threadIdx.x;  // 512
    out[tid] = bout[0];
    if (tid < NBR) g_barg[tid] = 0u;
    if (tid == 0) g_tbegin = T_ - 1;
}

// ---------------- per-row last-reset scan ----------------
__global__ void k_scan(const float* __restrict__ inp) {
    int b = blockIdx.x;
    int tid = threadIdx.x;  // 128
    int best = -1;
    for (int t = tid; t < T_ - 1; t += 128) {
        float v = inp[((size_t)t * B_ + b) * I_ + (I_ - 1)];
        if (v <= 0.0f) best = t;
    }
    __shared__ int red[128];
    red[tid] = best;
    __syncthreads();
    for (int off = 64; off; off >>= 1) {
        if (tid < off) red[tid] = max(red[tid], red[tid + off]);
        __syncthreads();
    }
    if (tid == 0) {
        int ts = red[0] + 1;
        g_tstart[b] = ts;
        atomicMin(&g_tbegin, ts);
    }
}

// ---------------- counting sort + prefix counts ----------------
__global__ void k_sortcnt() {
    __shared__ int hist[T_];
    __shared__ int bin[T_];
    __shared__ int wsum[32];
    int tid = threadIdx.x;  // 1024
    hist[tid] = 0;
    __syncthreads();
    if (tid < B_) atomicAdd(&hist[g_tstart[tid]], 1);
    __syncthreads();
    int v = hist[tid];
    int lane = tid & 31, w = tid >> 5;
    int x = v;
#pragma unroll
    for (int o = 1; o < 32; o <<= 1) {
        int y = __shfl_up_sync(0xffffffffu, x, o);
        if (lane >= o) x += y;
    }
    if (lane == 31) wsum[w] = x;
    __syncthreads();
    if (w == 0) {
        int y = wsum[lane];
#pragma unroll
        for (int o = 1; o < 32; o <<= 1) {
            int z = __shfl_up_sync(0xffffffffu, y, o);
            if (lane >= o) y += z;
        }
        wsum[lane] = y;
    }
    __syncthreads();
    int inc = x + (w ? wsum[w - 1] : 0);
    g_cnt[tid] = inc;
    bin[tid] = inc - v;
    __syncthreads();
    if (tid < B_) {
        int ts = g_tstart[tid];
        int pos = atomicAdd(&bin[ts], 1);
        g_perm[pos] = tid;
    }
}

__device__ __forceinline__ float sigf(float x) { return 1.0f / (1.0f + __expf(-x)); }

__device__ __forceinline__ void fma2(unsigned long long& acc, unsigned long long a,
                                     unsigned long long b) {
    asm("fma.rn.f32x2 %0, %1, %2, %0;" : "+l"(acc) : "l"(a), "l"(b));
}
__device__ __forceinline__ float unpack_sum(unsigned long long v) {
    float lo, hi;
    asm("mov.b64 {%0,%1}, %2;" : "=f"(lo), "=f"(hi) : "l"(v));
    return lo + hi;
}

// ---- compute NR rows (row = warp + 8q), K-half split over s2, packed f32x2 ----
template <int NR>
__device__ __forceinline__ void do_rows(
    const float* __restrict__ a_sh, const float4* __restrict__ wIF4,
    const float4* __restrict__ wGO4, int warp, int hc, int s2, int m0, int rgrp,
    int col, float4 myb, float* __restrict__ hwrite, const int* __restrict__ perm,
    float* __restrict__ cbuf, int n_prev, bool last, float wout_col,
    float* __restrict__ out)
{
    unsigned long long ai[NR], af[NR], ag[NR], ao[NR];
#pragma unroll
    for (int q = 0; q < NR; ++q) { ai[q] = af[q] = ag[q] = ao[q] = 0ull; }

    const int P0 = s2 * 96;
#pragma unroll 4
    for (int p = P0; p < P0 + 96; p += 2) {
        ulonglong2 wif0 = *(const ulonglong2*)&wIF4[(p    ) * 16 + hc];
        ulonglong2 wgo0 = *(const ulonglong2*)&wGO4[(p    ) * 16 + hc];
        ulonglong2 wif1 = *(const ulonglong2*)&wIF4[(p + 1) * 16 + hc];
        ulonglong2 wgo1 = *(const ulonglong2*)&wGO4[(p + 1) * 16 + hc];
#pragma unroll
        for (int q = 0; q < NR; ++q) {
            const ulonglong2 xx =
                *(const ulonglong2*)(a_sh + (warp + 8 * q) * AROW_STRIDE + 2 * p);
            fma2(ai[q], xx.x, wif0.x); fma2(af[q], xx.x, wif0.y);
            fma2(ag[q], xx.x, wgo0.x); fma2(ao[q], xx.x, wgo0.y);
            fma2(ai[q], xx.y, wif1.x); fma2(af[q], xx.y, wif1.y);
            fma2(ag[q], xx.y, wgo1.x); fma2(ao[q], xx.y, wgo1.y);
        }
    }

    const unsigned hmask = s2 ? 0xffff0000u : 0x0000ffffu;
#pragma unroll
    for (int q = 0; q < NR; ++q) {
        float si = unpack_sum(ai[q]);
        float sf = unpack_sum(af[q]);
        float sg = unpack_sum(ag[q]);
        float so = unpack_sum(ao[q]);
        // combine K-halves (full warp converged here)
        si += __shfl_xor_sync(0xffffffffu, si, 16);
        sf += __shfl_xor_sync(0xffffffffu, sf, 16);
        sg += __shfl_xor_sync(0xffffffffu, sg, 16);
        so += __shfl_xor_sync(0xffffffffu, so, 16);
        if ((q & 1) == s2) {   // uniform per 16-lane half
            int i = rgrp + (m0 + warp + 8 * q) * 8;
            int b = perm[i];
            float gi = sigf(si + myb.x);
            float gf = sigf(sf + myb.y);
            float gg = tanhf(sg + myb.z);
            float go = sigf(so + myb.w);
            float c  = (i >= n_prev) ? 0.0f : cbuf[b * H_ + col];
            float cn = gf * c + gi * gg;
            float hn = go * tanhf(cn);
            if (!last) {
                cbuf[b * H_ + col]   = cn;
                hwrite[b * H_ + col] = hn;
            } else {
                float vv = hn * wout_col;
                vv += __shfl_xor_sync(hmask, vv, 8);
                vv += __shfl_xor_sync(hmask, vv, 4);
                vv += __shfl_xor_sync(hmask, vv, 2);
                vv += __shfl_xor_sync(hmask, vv, 1);
                if (hc == 0) atomicAdd(&out[b], vv);
            }
        }
    }
}

// ---------------- persistent group-synced recurrence ----------------
__global__ void __launch_bounds__(256, 1) k_lstm(
    const float* __restrict__ inp, const float* __restrict__ Wih,
    const float* __restrict__ Whh, const float* __restrict__ bih,
    const float* __restrict__ bhh, const float* __restrict__ Wout,
    float* __restrict__ out)
{
    extern __shared__ float sm[];
    float4* wIF4  = (float4*)sm;                          // [192*16]: (i0,i1,f0,f1)
    float4* wGO4  = wIF4 + WPAIRS * 16;                   // [192*16]: (g0,g1,o0,o1)
    float*  a_sh  = sm + WPAIRS * 16 * 4 * 2;             // [32][392]
    float4* bias4 = (float4*)(a_sh + 32 * AROW_STRIDE);   // [16]

    const int rgrp = blockIdx.x & (NBR - 1);
    const int j    = blockIdx.x >> 3;
    const int tid  = threadIdx.x;

    // ---- repack weight slice into SMEM as (pair, hc, gates) ----
    for (int idx = tid; idx < WPAIRS * 16; idx += 256) {
        int p = idx >> 4, hc0 = idx & 15;
        int ch = j * HC + hc0;
        int k0 = 2 * p;
        const float* Wsrc; int kk, ld;
        if (k0 < I_) { Wsrc = Wih; kk = k0;      ld = I_; }
        else         { Wsrc = Whh; kk = k0 - I_; ld = H_; }
        float i0 = Wsrc[(0 * H_ + ch) * ld + kk], i1 = Wsrc[(0 * H_ + ch) * ld + kk + 1];
        float f0 = Wsrc[(1 * H_ + ch) * ld + kk], f1 = Wsrc[(1 * H_ + ch) * ld + kk + 1];
        float g0 = Wsrc[(2 * H_ + ch) * ld + kk], g1 = Wsrc[(2 * H_ + ch) * ld + kk + 1];
        float o0 = Wsrc[(3 * H_ + ch) * ld + kk], o1 = Wsrc[(3 * H_ + ch) * ld + kk + 1];
        wIF4[idx] = make_float4(i0, i1, f0, f1);
        wGO4[idx] = make_float4(g0, g1, o0, o1);
    }
    if (tid < 16) {
        int ch = j * HC + tid;
        float4 bb;
        bb.x = bih[0 * H_ + ch] + bhh[0 * H_ + ch];
        bb.y = bih[1 * H_ + ch] + bhh[1 * H_ + ch];
        bb.z = bih[2 * H_ + ch] + bhh[2 * H_ + ch];
        bb.w = bih[3 * H_ + ch] + bhh[3 * H_ + ch];
        bias4[tid] = bb;
    }
    __syncthreads();

    const int warp = tid >> 5, lane = tid & 31;
    const int hc = lane & 15, s2 = lane >> 4;
    const int col = j * HC + hc;
    const float4 myb = bias4[hc];
    const float wout_col = Wout[col];

    const int tb = g_tbegin;
    unsigned step = 0;

    for (int t = tb; t < T_; ++t) {
        const int n = g_cnt[t];
        const int n_prev = (t > 0) ? g_cnt[t - 1] : 0;
        const float* __restrict__ hread = g_hbuf[t & 1];
        float* __restrict__ hwrite = g_hbuf[(t + 1) & 1];
        const int mcount = (n > rgrp) ? ((n - rgrp + NBR - 1) >> 3) : 0;
        const bool last = (t == T_ - 1);

        for (int m0 = 0; m0 < mcount; m0 += 32) {
            const int chunk = min(32, mcount - m0);

            // ---- stage up to 32 active rows: [x_t(128) | h(256)] ----
            {
                int mm = tid >> 3, l8 = tid & 7;
                if (mm < chunk) {
                    int i = rgrp + (m0 + mm) * 8;
                    int b = g_perm[i];
                    const float4* xin = (const float4*)(inp + ((size_t)t * B_ + b) * I_);
                    float4* arow = (float4*)(a_sh + mm * AROW_STRIDE);
#pragma unroll
                    for (int q = 0; q < 4; ++q) arow[l8 + 8 * q] = xin[l8 + 8 * q];
                    if (i >= n_prev) {
                        float4 z = make_float4(0.f, 0.f, 0.f, 0.f);
#pragma unroll
                        for (int q = 0; q < 8; ++q) arow[32 + l8 + 8 * q] = z;
                    } else {
                        const float4* hin = (const float4*)(hread + b * H_);
#pragma unroll
                        for (int q = 0; q < 8; ++q) arow[32 + l8 + 8 * q] = hin[l8 + 8 * q];
                    }
                }
            }
            __syncthreads();

            const int avail = chunk - warp;
            if (avail > 0) {
                const int nr = ((avail - 1) >> 3) + 1;  // rows for this warp: warp+8q
                switch (nr) {
                    case 1: do_rows<1>(a_sh, wIF4, wGO4, warp, hc, s2, m0, rgrp, col, myb,
                                       hwrite, g_perm, g_cbuf, n_prev, last, wout_col, out); break;
                    case 2: do_rows<2>(a_sh, wIF4, wGO4, warp, hc, s2, m0, rgrp, col, myb,
                                       hwrite, g_perm, g_cbuf, n_prev, last, wout_col, out); break;
                    case 3: do_rows<3>(a_sh, wIF4, wGO4, warp, hc, s2, m0, rgrp, col, myb,
                                       hwrite, g_perm, g_cbuf, n_prev, last, wout_col, out); break;
                    default: do_rows<4>(a_sh, wIF4, wGO4, warp, hc, s2, m0, rgrp, col, myb,
                                        hwrite, g_perm, g_cbuf, n_prev, last, wout_col, out); break;
                }
            }
            __syncthreads();
        }

        if (last) break;

        // ---- per-r-group software barrier (16 CTAs) ----
        step++;
        __syncthreads();
        if (tid == 0) {
            __threadfence();
            atomicAdd(&g_barg[rgrp], 1u);
            unsigned target = step * (unsigned)NHC;
            unsigned v;
            do {
                asm volatile("ld.acquire.gpu.u32 %0, [%1];" : "=r"(v) : "l"(&g_barg[rgrp]) : "memory");
            } while (v < target);
        }
        __syncthreads();
    }
}

extern "C" void kernel_launch(void* const* d_in, const int* in_sizes, int n_in,
                              void* d_out, int out_size) {
    (void)in_sizes; (void)n_in; (void)out_size;
    const float* inp  = (const float*)d_in[0];
    const float* Wih  = (const float*)d_in[1];
    const float* Whh  = (const float*)d_in[2];
    const float* bih  = (const float*)d_in[3];
    const float* bhh  = (const float*)d_in[4];
    const float* Wout = (const float*)d_in[5];
    const float* bout = (const float*)d_in[6];
    float* out = (float*)d_out;

    cudaFuncSetAttribute(k_lstm, cudaFuncAttributeMaxDynamicSharedMemorySize, SMEM_BYTES);

    k_zero<<<1, 512>>>(bout, out);
    k_scan<<<B_, 128>>>(inp);
    k_sortcnt<<<1, 1024>>>();
    k_lstm<<<NCTA, 256, SMEM_BYTES>>>(inp, Wih, Whh, bih, bhh, Wout, out);
}